// round 15
// baseline (speedup 1.0000x reference)
#include <cuda_runtime.h>
#include <cuda_fp16.h>
#include <math.h>
#include <stdint.h>

// Problem constants
#define Bsz 4
#define Sq  2048
#define Dm  768
#define Im  1536
#define Dh  128
#define Mtot (Bsz*Sq)   // 8192

#define BM 128
#define BN 128
#define BK 32                 // K elements (halves) per smem tile
#define NT 128
#define STAGES 4

// smem geometry (halves): tiles [row][k], stride 40 halves (32 + 8 pad)
#define A_ST 40
#define A_SZ (BM*A_ST)                       // 5120 halves / stage
#define SMEM_BYTES (STAGES*2*A_SZ*2)         // 81920 B

// V^T staging tile: [128 c][68] halves
#define VT_ST 68

// Scratch (device globals). fp16 operands; gate + bias fp32.
__device__ __align__(16) __half g_Xh [Mtot*Dm];    // h(x)
__device__ __align__(16) __half g_vWh[Im*Dm];      // h(v_W^T)   [Im][Dm]
__device__ __align__(16) __half g_gWh[Im*Dm];      // h(g_W^T)
__device__ __align__(16) __half g_inWh[Dh*Dm];     // h(in_W^T)  [Dh][Dm]
__device__ __align__(16) __half g_oWh[Dm*Im];      // h(out_W^T) [Dm][Im]
__device__ __align__(16) __half g_Vh[Mtot*Im];     // h(V^T) per batch [Bsz][Im][Sq]
__device__ float  g_G[Mtot*Im];                    // f32 gate, [m][Im]
__device__ __align__(16) __half g_Qh[Mtot*Dh];
__device__ __align__(16) __half g_Kh[Mtot*Dh];
__device__ __align__(16) __half g_Ah[(size_t)Bsz*Sq*Sq];  // scores
__device__ __align__(16) __half g_Oh[Mtot*Im];     // (A@V)*G
__device__ float g_bias[Sq];                       // bias by causal distance

// ---------------------------------------------------------------------------
// helpers
// ---------------------------------------------------------------------------
__device__ __forceinline__ void cp16(uint32_t dst, const void* src)
{
    asm volatile("cp.async.cg.shared.global [%0], [%1], 16;"
                 :: "r"(dst), "l"(src));
}

__device__ __forceinline__ void ldsm4(uint32_t (&r)[4], uint32_t addr)
{
    asm volatile("ldmatrix.sync.aligned.m8n8.x4.shared.b16 {%0,%1,%2,%3}, [%4];"
                 : "=r"(r[0]), "=r"(r[1]), "=r"(r[2]), "=r"(r[3]) : "r"(addr));
}

__device__ __forceinline__ void mma16(float (&d)[4], const uint32_t (&a)[4],
                                      const uint32_t (&b)[2])
{
    asm volatile(
        "mma.sync.aligned.m16n8k16.row.col.f32.f16.f16.f32 "
        "{%0,%1,%2,%3}, {%4,%5,%6,%7}, {%8,%9}, {%0,%1,%2,%3};"
        : "+f"(d[0]), "+f"(d[1]), "+f"(d[2]), "+f"(d[3])
        : "r"(a[0]), "r"(a[1]), "r"(a[2]), "r"(a[3]), "r"(b[0]), "r"(b[1]));
}

__device__ __forceinline__ float silu_f(float x)
{
    return x / (1.0f + __expf(-x));
}

extern __shared__ __align__(16) float sm_dyn[];

// ---------------------------------------------------------------------------
// Prologue kernels
// ---------------------------------------------------------------------------
__global__ void bias_init_kernel(const float* __restrict__ rel_emb)
{
    int d = blockIdx.x * blockDim.x + threadIdx.x;
    if (d >= Sq) return;
    int bucket;
    if (d < 16) {
        bucket = d;
    } else {
        int v = 16 + (int)(log((double)d / 16.0) / log(8.0) * 16.0);
        bucket = v < 31 ? v : 31;
    }
    g_bias[d] = rel_emb[bucket] * sqrtf((float)Dh);
}

__global__ void cvt_x_kernel(const float* __restrict__ x)
{
    int i = blockIdx.x * blockDim.x + threadIdx.x;   // float4 index
    float4 v = ((const float4*)x)[i];
    __half2* dst = (__half2*)g_Xh;
    dst[i * 2 + 0] = __floats2half2_rn(v.x, v.y);
    dst[i * 2 + 1] = __floats2half2_rn(v.z, v.w);
}

// Wt[n][k] = h(W[k][n]).  W: K x N.  256 threads = 32x8, 32x32 tiles.
__global__ void transpose_cvt_kernel(const float* __restrict__ W,
                                     int K, int N, int which)
{
    __half* __restrict__ Wt = (which == 0) ? g_vWh :
                              (which == 1) ? g_gWh :
                              (which == 2) ? g_inWh : g_oWh;
    __shared__ float t[32][33];
    int k0 = blockIdx.y * 32, n0 = blockIdx.x * 32;
    int tx = threadIdx.x & 31, ty = threadIdx.x >> 5;
    #pragma unroll
    for (int i = ty; i < 32; i += 8)
        t[i][tx] = W[(size_t)(k0 + i) * N + n0 + tx];
    __syncthreads();
    #pragma unroll
    for (int i = ty; i < 32; i += 8)
        Wt[(size_t)(n0 + i) * K + k0 + tx] = __float2half_rn(t[tx][i]);
}

// ---------------------------------------------------------------------------
// Pipelined fp16 tensor-core GEMM core: 128x128 CTA tile, 4 warps of 64x64,
// mma m16n8k16 f16->f32, 4-stage cp.async (2 in flight), fragment loads for
// the whole K-tile hoisted ahead of the MMA block.
// A: [M][K] row-major halves.  Bt: [N][K] row-major halves.
// acc[mt 0..3][nt 0..7][4]
// ---------------------------------------------------------------------------
__device__ __forceinline__ void run_mma(
    const __half* __restrict__ A, int lda, int rowBase,
    const __half* __restrict__ Bt, int ldb, int colBase,
    int kEnd, float (&acc)[4][8][4])
{
    const int tid  = threadIdx.x;
    const int lane = tid & 31;
    const int warp = tid >> 5;
    const int m0w  = (warp >> 1) * 64;
    const int n0w  = (warp & 1) * 64;
    const int ktiles = kEnd / BK;

    // cp.async mapping: thread tid owns row tid of both tiles (4 x 16B each)
    const __half* aSrc = A  + (size_t)(rowBase + tid) * lda;
    const __half* bSrc = Bt + (size_t)(colBase + tid) * ldb;
    const uint32_t sBase = (uint32_t)__cvta_generic_to_shared(sm_dyn);
    const uint32_t aDst0 = sBase + (uint32_t)(tid * A_ST) * 2u;
    const uint32_t bDst0 = sBase + (uint32_t)(STAGES * A_SZ + tid * A_ST) * 2u;

    #define LOAD_TILE(kt, slot)                                     \
    do {                                                            \
        uint32_t ad_ = aDst0 + (uint32_t)((slot) * A_SZ) * 2u;      \
        const __half* as_ = aSrc + (size_t)(kt) * BK;               \
        cp16(ad_,       as_);                                       \
        cp16(ad_ + 16u, as_ + 8);                                   \
        cp16(ad_ + 32u, as_ + 16);                                  \
        cp16(ad_ + 48u, as_ + 24);                                  \
        uint32_t bd_ = bDst0 + (uint32_t)((slot) * A_SZ) * 2u;      \
        const __half* bs_ = bSrc + (size_t)(kt) * BK;               \
        cp16(bd_,       bs_);                                       \
        cp16(bd_ + 16u, bs_ + 8);                                   \
        cp16(bd_ + 32u, bs_ + 16);                                  \
        cp16(bd_ + 48u, bs_ + 24);                                  \
    } while (0)

    // prologue: fill STAGES-1 = 3 slots  (ktiles >= 4 in all call sites)
    LOAD_TILE(0, 0);
    asm volatile("cp.async.commit_group;");
    LOAD_TILE(1, 1);
    asm volatile("cp.async.commit_group;");
    LOAD_TILE(2, 2);
    asm volatile("cp.async.commit_group;");

    // ldmatrix lane offsets (identical for A and B with b16 elements)
    const int rowOff = (lane & 7) + 8 * ((lane >> 3) & 1);
    const int colOff = (lane >> 4) * 8;     // halves

    int slot = 0;
    for (int kt = 0; kt < ktiles; kt++) {
        asm volatile("cp.async.wait_group 2;");
        __syncthreads();

        int nkt = kt + STAGES - 1;
        if (nkt < ktiles) {
            int ns = slot + STAGES - 1;
            if (ns >= STAGES) ns -= STAGES;
            LOAD_TILE(nkt, ns);
        }
        asm volatile("cp.async.commit_group;");

        const uint32_t asl = sBase + (uint32_t)(slot * A_SZ) * 2u;
        const uint32_t bsl = sBase + (uint32_t)((STAGES + slot) * A_SZ) * 2u;

        // hoist ALL fragment loads for this K-tile (both ks halves), then MMA
        uint32_t af[2][4][4], bf[2][8][2];
        #pragma unroll
        for (int s = 0; s < 2; s++) {
            const int ks = s * 16;
            #pragma unroll
            for (int mt = 0; mt < 4; mt++)
                ldsm4(af[s][mt], asl +
                      (uint32_t)((m0w + mt * 16 + rowOff) * A_ST + ks + colOff) * 2u);
            #pragma unroll
            for (int np = 0; np < 4; np++) {
                uint32_t t[4];
                ldsm4(t, bsl +
                      (uint32_t)((n0w + np * 16 + rowOff) * A_ST + ks + colOff) * 2u);
                bf[s][2 * np][0]     = t[0]; bf[s][2 * np][1]     = t[2];
                bf[s][2 * np + 1][0] = t[1]; bf[s][2 * np + 1][1] = t[3];
            }
        }
        #pragma unroll
        for (int s = 0; s < 2; s++)
            #pragma unroll
            for (int mt = 0; mt < 4; mt++)
                #pragma unroll
                for (int nt = 0; nt < 8; nt++)
                    mma16(acc[mt][nt], af[s][mt], bf[s][nt]);

        if (++slot == STAGES) slot = 0;
    }
    #undef LOAD_TILE
}

#define ACC_INIT(acc)                                   \
    _Pragma("unroll")                                   \
    for (int mt = 0; mt < 4; mt++)                      \
        _Pragma("unroll")                               \
        for (int nt = 0; nt < 8; nt++)                  \
            _Pragma("unroll")                           \
            for (int e = 0; e < 4; e++) acc[mt][nt][e] = 0.0f;

// Element (mt, nt, h, j):
//   row = rowBase + (warp>>1)*64 + mt*16 + (lane>>2) + h*8
//   col = colBase + (warp&1)*64 + nt*8 + (lane&3)*2 + j
#define EPI_PREAMBLE                                       \
    const int tid  = threadIdx.x;                          \
    const int lane = tid & 31;                             \
    const int warp = tid >> 5;                             \
    const int mBase = (warp >> 1) * 64 + (lane >> 2);      \
    const int nBase = (warp & 1) * 64 + (lane & 3) * 2;

// ---------------------------------------------------------------------------
// V (which=0): silu -> half, stored transposed per batch [Im][Sq] via smem.
// G (which=1): silu -> f32, [m][Im]
// ---------------------------------------------------------------------------
__global__ void __launch_bounds__(NT, 2)
gemm_silu_kernel(const float* __restrict__ bias, int which)
{
    float acc[4][8][4];
    ACC_INIT(acc);
    run_mma(g_Xh, Dm, blockIdx.y * BM, which ? g_gWh : g_vWh, Dm,
            blockIdx.x * BN, Dm, acc);

    EPI_PREAMBLE;
    const int col0 = blockIdx.x * BN + nBase;
    if (which) {
        const int row0 = blockIdx.y * BM + mBase;
        #pragma unroll
        for (int mt = 0; mt < 4; mt++)
            #pragma unroll
            for (int nt = 0; nt < 8; nt++) {
                int c = col0 + nt * 8;
                float b0 = bias[c], b1 = bias[c + 1];
                #pragma unroll
                for (int h = 0; h < 2; h++) {
                    int r = row0 + mt * 16 + h * 8;
                    float2 o;
                    o.x = silu_f(acc[mt][nt][2 * h + 0] + b0);
                    o.y = silu_f(acc[mt][nt][2 * h + 1] + b1);
                    *(float2*)&g_G[(size_t)r * Im + c] = o;
                }
            }
    } else {
        // V^T: stage each 64-row (s) half of the tile in smem as [c][s] halves.
        const int b  = (blockIdx.y * BM) / Sq;
        const int sTile = blockIdx.y * BM - b * Sq;
        __half* __restrict__ Vt = g_Vh + (size_t)b * Im * Sq;
        __half* ts = (__half*)sm_dyn;                       // [128][VT_ST]

        asm volatile("cp.async.wait_all;");
        __syncthreads();                                    // ring buffer dead

        const int myHalf = warp >> 1;
        const int sLoc   = lane >> 2;
        #pragma unroll
        for (int h2 = 0; h2 < 2; h2++) {
            if (myHalf == h2) {
                #pragma unroll
                for (int mt = 0; mt < 4; mt++)
                    #pragma unroll
                    for (int nt = 0; nt < 8; nt++) {
                        int c = nBase + nt * 8;
                        float b0 = bias[col0 + nt * 8], b1 = bias[col0 + nt * 8 + 1];
                        #pragma unroll
                        for (int hh = 0; hh < 2; hh++) {
                            int s = sLoc + mt * 16 + hh * 8;     // 0..63
                            float v0 = silu_f(acc[mt][nt][2 * hh + 0] + b0);
                            float v1 = silu_f(acc[mt][nt][2 * hh + 1] + b1);
                            ts[c * VT_ST + s]       = __float2half_rn(v0);
                            ts[(c + 1) * VT_ST + s] = __float2half_rn(v1);
                        }
                    }
            }
            __syncthreads();
            // 128 threads store 128 c-rows x 64 s halves (uint2 = 4 halves)
            #pragma unroll
            for (int p = 0; p < 16; p++) {
                int idx = tid + p * NT;          // 0..2047
                int c  = idx >> 4;               // 0..127
                int s4 = (idx & 15) << 2;        // 0..60
                uint2 v = *(const uint2*)&ts[c * VT_ST + s4];
                *(uint2*)&Vt[(size_t)(blockIdx.x * BN + c) * Sq
                             + sTile + h2 * 64 + s4] = v;
            }
            __syncthreads();
        }
    }
}

// ---------------------------------------------------------------------------
// base = silu(X @ inW + inb);  Q/K = affine(base), half
// ---------------------------------------------------------------------------
__global__ void __launch_bounds__(NT, 2)
gemm_qk_kernel(const float* __restrict__ inb,
               const float* __restrict__ qg, const float* __restrict__ qb,
               const float* __restrict__ kg, const float* __restrict__ kb)
{
    float acc[4][8][4];
    ACC_INIT(acc);
    run_mma(g_Xh, Dm, blockIdx.y * BM, g_inWh, Dm, 0, Dm, acc);

    EPI_PREAMBLE;
    const int row0 = blockIdx.y * BM + mBase;
    #pragma unroll
    for (int mt = 0; mt < 4; mt++)
        #pragma unroll
        for (int nt = 0; nt < 8; nt++) {
            int c = nBase + nt * 8;
            float g0q = qg[c], g1q = qg[c + 1], b0q = qb[c], b1q = qb[c + 1];
            float g0k = kg[c], g1k = kg[c + 1], b0k = kb[c], b1k = kb[c + 1];
            float i0 = inb[c], i1 = inb[c + 1];
            #pragma unroll
            for (int h = 0; h < 2; h++) {
                int r = row0 + mt * 16 + h * 8;
                float s0 = silu_f(acc[mt][nt][2 * h + 0] + i0);
                float s1 = silu_f(acc[mt][nt][2 * h + 1] + i1);
                size_t idx = (size_t)r * Dh + c;
                *(__half2*)&g_Qh[idx] =
                    __floats2half2_rn(s0 * g0q + b0q, s1 * g1q + b1q);
                *(__half2*)&g_Kh[idx] =
                    __floats2half2_rn(s0 * g0k + b0k, s1 * g1k + b1k);
            }
        }
}

// ---------------------------------------------------------------------------
// A[b] = relu(Q K^T / sqrt(1536) + bias)^2, causal; half out.
// Strictly-upper tiles never read downstream -> early exit.
// ---------------------------------------------------------------------------
__global__ void __launch_bounds__(NT, 2)
scores_kernel()
{
    if (blockIdx.x > blockIdx.y) return;

    const int z  = blockIdx.z;
    const int i0 = blockIdx.y * BM;
    const int j0 = blockIdx.x * BN;
    __half* __restrict__ Ab = g_Ah + (size_t)z * Sq * Sq;

    float acc[4][8][4];
    ACC_INIT(acc);
    run_mma(g_Qh + (size_t)z * Sq * Dh, Dh, i0,
            g_Kh + (size_t)z * Sq * Dh, Dh, j0, Dh, acc);

    EPI_PREAMBLE;
    const float rscale = 1.0f / sqrtf((float)Im);
    const int gi0 = i0 + mBase;
    const int gj0 = j0 + nBase;
    #pragma unroll
    for (int mt = 0; mt < 4; mt++)
        #pragma unroll
        for (int nt = 0; nt < 8; nt++) {
            #pragma unroll
            for (int h = 0; h < 2; h++) {
                int gi = gi0 + mt * 16 + h * 8;
                int gj = gj0 + nt * 8;
                float v0 = 0.0f, v1 = 0.0f;
                if (gj <= gi) {
                    float s = acc[mt][nt][2 * h] * rscale + g_bias[gi - gj];
                    v0 = (s > 0.0f) ? s * s : 0.0f;
                }
                if (gj + 1 <= gi) {
                    float s = acc[mt][nt][2 * h + 1] * rscale + g_bias[gi - gj - 1];
                    v1 = (s > 0.0f) ? s * s : 0.0f;
                }
                *(__half2*)&Ab[(size_t)gi * Sq + gj] = __floats2half2_rn(v0, v1);
            }
        }
}

// ---------------------------------------------------------------------------
// O[b] = (A[b] @ V[b]) * G[b]; half out.  Causal k-limit.
// ---------------------------------------------------------------------------
__global__ void __launch_bounds__(NT, 2)
gemm_av_gate_kernel()
{
    const int z = blockIdx.z;
    float acc[4][8][4];
    ACC_INIT(acc);
    const int kEnd = blockIdx.y * BM + BM;
    run_mma(g_Ah + (size_t)z * Sq * Sq, Sq, blockIdx.y * BM,
            g_Vh + (size_t)z * Im * Sq, Sq, blockIdx.x * BN, kEnd, acc);

    EPI_PREAMBLE;
    const int row0 = z * Sq + blockIdx.y * BM + mBase;
    const int col0 = blockIdx.x * BN + nBase;
    #pragma unroll
    for (int mt = 0; mt < 4; mt++)
        #pragma unroll
        for (int nt = 0; nt < 8; nt++) {
            int c = col0 + nt * 8;
            #pragma unroll
            for (int h = 0; h < 2; h++) {
                int r = row0 + mt * 16 + h * 8;
                size_t idx = (size_t)r * Im + c;
                float2 g = *(const float2*)&g_G[idx];
                *(__half2*)&g_Oh[idx] =
                    __floats2half2_rn(acc[mt][nt][2 * h + 0] * g.x,
                                      acc[mt][nt][2 * h + 1] * g.y);
            }
        }
}

// ---------------------------------------------------------------------------
// out = O @ out_W + out_b   (f32 output)
// ---------------------------------------------------------------------------
__global__ void __launch_bounds__(NT, 2)
gemm_out_kernel(const float* __restrict__ bias, float* __restrict__ out)
{
    float acc[4][8][4];
    ACC_INIT(acc);
    run_mma(g_Oh, Im, blockIdx.y * BM, g_oWh, Im, blockIdx.x * BN, Im, acc);

    EPI_PREAMBLE;
    const int row0 = blockIdx.y * BM + mBase;
    const int col0 = blockIdx.x * BN + nBase;
    #pragma unroll
    for (int mt = 0; mt < 4; mt++)
        #pragma unroll
        for (int nt = 0; nt < 8; nt++) {
            int c = col0 + nt * 8;
            float b0 = bias[c], b1 = bias[c + 1];
            #pragma unroll
            for (int h = 0; h < 2; h++) {
                int r = row0 + mt * 16 + h * 8;
                float2 o;
                o.x = acc[mt][nt][2 * h + 0] + b0;
                o.y = acc[mt][nt][2 * h + 1] + b1;
                *(float2*)&out[(size_t)r * Dm + c] = o;
            }
        }
}

// ---------------------------------------------------------------------------
// Launch (input order auto-detected from in_sizes[0])
// ---------------------------------------------------------------------------
extern "C" void kernel_launch(void* const* d_in, const int* in_sizes, int n_in,
                              void* d_out, int out_size)
{
    const float *x, *vW, *vb, *gW, *gb, *inW, *inb;
    const float *qg, *qb, *kg, *kb, *oW, *ob, *rel;

    if (in_sizes[0] == Bsz * Sq * Dm) {
        x   = (const float*)d_in[0];
        vW  = (const float*)d_in[1];
        vb  = (const float*)d_in[2];
        gW  = (const float*)d_in[3];
        gb  = (const float*)d_in[4];
        inW = (const float*)d_in[5];
        inb = (const float*)d_in[6];
        qg  = (const float*)d_in[7];
        qb  = (const float*)d_in[8];
        kg  = (const float*)d_in[9];
        kb  = (const float*)d_in[10];
        oW  = (const float*)d_in[11];
        ob  = (const float*)d_in[12];
        rel = (const float*)d_in[13];
    } else {
        gW  = (const float*)d_in[0];
        gb  = (const float*)d_in[1];
        inW = (const float*)d_in[2];
        inb = (const float*)d_in[3];
        kb  = (const float*)d_in[4];
        kg  = (const float*)d_in[5];
        oW  = (const float*)d_in[6];
        ob  = (const float*)d_in[7];
        qb  = (const float*)d_in[8];
        qg  = (const float*)d_in[9];
        rel = (const float*)d_in[10];
        vW  = (const float*)d_in[11];
        vb  = (const float*)d_in[12];
        x   = (const float*)d_in[13];
    }

    float* out = (float*)d_out;

    static bool attr_done = false;
    if (!attr_done) {
        cudaFuncSetAttribute(gemm_silu_kernel,
            cudaFuncAttributeMaxDynamicSharedMemorySize, SMEM_BYTES);
        cudaFuncSetAttribute(gemm_qk_kernel,
            cudaFuncAttributeMaxDynamicSharedMemorySize, SMEM_BYTES);
        cudaFuncSetAttribute(scores_kernel,
            cudaFuncAttributeMaxDynamicSharedMemorySize, SMEM_BYTES);
        cudaFuncSetAttribute(gemm_av_gate_kernel,
            cudaFuncAttributeMaxDynamicSharedMemorySize, SMEM_BYTES);
        cudaFuncSetAttribute(gemm_out_kernel,
            cudaFuncAttributeMaxDynamicSharedMemorySize, SMEM_BYTES);
        attr_done = true;
    }

    // prologue: bias LUT, x->fp16, weight transposes (+cvt)
    bias_init_kernel<<<(Sq + 255) / 256, 256>>>(rel);
    cvt_x_kernel<<<(Mtot * Dm / 4 + 255) / 256, 256>>>(x);
    transpose_cvt_kernel<<<dim3(Im / 32, Dm / 32), 256>>>(vW,  Dm, Im, 0);
    transpose_cvt_kernel<<<dim3(Im / 32, Dm / 32), 256>>>(gW,  Dm, Im, 1);
    transpose_cvt_kernel<<<dim3(Dh / 32, Dm / 32), 256>>>(inW, Dm, Dh, 2);
    transpose_cvt_kernel<<<dim3(Dm / 32, Im / 32), 256>>>(oW,  Im, Dm, 3);

    dim3 blk(NT);
    gemm_silu_kernel<<<dim3(Im / BN, Mtot / BM), blk, SMEM_BYTES>>>(vb, 0);
    gemm_silu_kernel<<<dim3(Im / BN, Mtot / BM), blk, SMEM_BYTES>>>(gb, 1);
    gemm_qk_kernel  <<<dim3(1,       Mtot / BM), blk, SMEM_BYTES>>>(inb, qg, qb, kg, kb);
    scores_kernel   <<<dim3(Sq / BN, Sq / BM, Bsz), blk, SMEM_BYTES>>>();
    gemm_av_gate_kernel<<<dim3(Im / BN, Sq / BM, Bsz), blk, SMEM_BYTES>>>();
    gemm_out_kernel <<<dim3(Dm / BN, Mtot / BM), blk, SMEM_BYTES>>>(ob, out);
}

// round 16
// speedup vs baseline: 1.0775x; 1.0775x over previous
#include <cuda_runtime.h>
#include <cuda_fp16.h>
#include <math.h>
#include <stdint.h>

// Problem constants
#define Bsz 4
#define Sq  2048
#define Dm  768
#define Im  1536
#define Dh  128
#define Mtot (Bsz*Sq)   // 8192

#define BM 128
#define BN 128
#define BK 32                 // K elements (halves) per smem tile
#define NT 128
#define STAGES 3

// smem geometry (halves): tiles [row][k], stride 40 halves (32 + 8 pad)
#define A_ST 40
#define A_SZ (BM*A_ST)                       // 5120 halves / stage
#define SMEM_BYTES (STAGES*2*A_SZ*2)         // 61440 B

// qk (BM=64) variant geometry
#define A_SZ64 (64*A_ST)                     // 2560 halves / stage
#define SMEM_BYTES64 (STAGES*(A_SZ64 + A_SZ)*2)   // 46080 B

// V^T staging tile: [128 c][68] halves
#define VT_ST 68

// Scratch (device globals). fp16 operands; gate + bias fp32.
__device__ __align__(16) __half g_Xh [Mtot*Dm];    // h(x)
__device__ __align__(16) __half g_vWh[Im*Dm];      // h(v_W^T)   [Im][Dm]
__device__ __align__(16) __half g_gWh[Im*Dm];      // h(g_W^T)
__device__ __align__(16) __half g_inWh[Dh*Dm];     // h(in_W^T)  [Dh][Dm]
__device__ __align__(16) __half g_oWh[Dm*Im];      // h(out_W^T) [Dm][Im]
__device__ __align__(16) __half g_Vh[Mtot*Im];     // h(V^T) per batch [Bsz][Im][Sq]
__device__ float  g_G[Mtot*Im];                    // f32 gate, [m][Im]
__device__ __align__(16) __half g_Qh[Mtot*Dh];
__device__ __align__(16) __half g_Kh[Mtot*Dh];
__device__ __align__(16) __half g_Ah[(size_t)Bsz*Sq*Sq];  // scores
__device__ __align__(16) __half g_Oh[Mtot*Im];     // (A@V)*G
__device__ float g_bias[Sq];                       // bias by causal distance

// ---------------------------------------------------------------------------
// helpers
// ---------------------------------------------------------------------------
__device__ __forceinline__ void cp16(uint32_t dst, const void* src)
{
    asm volatile("cp.async.cg.shared.global [%0], [%1], 16;"
                 :: "r"(dst), "l"(src));
}

__device__ __forceinline__ void ldsm4(uint32_t (&r)[4], uint32_t addr)
{
    asm volatile("ldmatrix.sync.aligned.m8n8.x4.shared.b16 {%0,%1,%2,%3}, [%4];"
                 : "=r"(r[0]), "=r"(r[1]), "=r"(r[2]), "=r"(r[3]) : "r"(addr));
}

__device__ __forceinline__ void mma16(float (&d)[4], const uint32_t (&a)[4],
                                      const uint32_t (&b)[2])
{
    asm volatile(
        "mma.sync.aligned.m16n8k16.row.col.f32.f16.f16.f32 "
        "{%0,%1,%2,%3}, {%4,%5,%6,%7}, {%8,%9}, {%0,%1,%2,%3};"
        : "+f"(d[0]), "+f"(d[1]), "+f"(d[2]), "+f"(d[3])
        : "r"(a[0]), "r"(a[1]), "r"(a[2]), "r"(a[3]), "r"(b[0]), "r"(b[1]));
}

__device__ __forceinline__ float silu_f(float x)
{
    return x / (1.0f + __expf(-x));
}

extern __shared__ __align__(16) float sm_dyn[];

// ---------------------------------------------------------------------------
// Fused prologue: one launch does bias LUT, x->fp16, and 4 weight
// transposes (fp32 -> fp16^T), dispatched by blockIdx.x range.
// 256 threads per block.
// ---------------------------------------------------------------------------
#define NB_BIAS 8
#define NB_X    (Mtot*Dm/4/256)        // 6144
#define NB_VW   ((Im/32)*(Dm/32))      // 1152
#define NB_INW  ((Dh/32)*(Dm/32))      // 96
#define NB_OW   ((Dm/32)*(Im/32))      // 1152
#define PRO_B0  NB_BIAS
#define PRO_B1  (PRO_B0 + NB_X)
#define PRO_B2  (PRO_B1 + NB_VW)
#define PRO_B3  (PRO_B2 + NB_VW)
#define PRO_B4  (PRO_B3 + NB_INW)
#define PRO_TOT (PRO_B4 + NB_OW)

__device__ __forceinline__ void transpose_tile(
    const float* __restrict__ W, __half* __restrict__ Wt,
    int K, int N, int id)
{
    __shared__ float t[32][33];
    int n0 = (id % (N / 32)) * 32;
    int k0 = (id / (N / 32)) * 32;
    int tx = threadIdx.x & 31, ty = threadIdx.x >> 5;
    #pragma unroll
    for (int i = ty; i < 32; i += 8)
        t[i][tx] = W[(size_t)(k0 + i) * N + n0 + tx];
    __syncthreads();
    #pragma unroll
    for (int i = ty; i < 32; i += 8)
        Wt[(size_t)(n0 + i) * K + k0 + tx] = __float2half_rn(t[tx][i]);
}

__global__ void fused_prologue_kernel(
    const float* __restrict__ x,  const float* __restrict__ vW,
    const float* __restrict__ gW, const float* __restrict__ inW,
    const float* __restrict__ oW, const float* __restrict__ rel)
{
    const int bid = blockIdx.x;
    if (bid < PRO_B0) {
        int d = bid * 256 + threadIdx.x;
        if (d < Sq) {
            int bucket;
            if (d < 16) {
                bucket = d;
            } else {
                int v = 16 + (int)(log((double)d / 16.0) / log(8.0) * 16.0);
                bucket = v < 31 ? v : 31;
            }
            g_bias[d] = rel[bucket] * sqrtf((float)Dh);
        }
    } else if (bid < PRO_B1) {
        int i = (bid - PRO_B0) * 256 + threadIdx.x;   // float4 index
        float4 v = ((const float4*)x)[i];
        __half2* dst = (__half2*)g_Xh;
        dst[i * 2 + 0] = __floats2half2_rn(v.x, v.y);
        dst[i * 2 + 1] = __floats2half2_rn(v.z, v.w);
    } else if (bid < PRO_B2) {
        transpose_tile(vW, g_vWh, Dm, Im, bid - PRO_B1);
    } else if (bid < PRO_B3) {
        transpose_tile(gW, g_gWh, Dm, Im, bid - PRO_B2);
    } else if (bid < PRO_B4) {
        transpose_tile(inW, g_inWh, Dm, Dh, bid - PRO_B3);
    } else {
        transpose_tile(oW, g_oWh, Im, Dm, bid - PRO_B4);
    }
}

// ---------------------------------------------------------------------------
// Pipelined fp16 tensor-core GEMM core: 128x128 CTA tile, 4 warps of 64x64,
// mma m16n8k16 f16->f32, 3-stage cp.async, ldmatrix.x4.b16 fragments.
// A: [M][K] row-major halves.  Bt: [N][K] row-major halves.
// acc[mt 0..3][nt 0..7][4]
// ---------------------------------------------------------------------------
__device__ __forceinline__ void run_mma(
    const __half* __restrict__ A, int lda, int rowBase,
    const __half* __restrict__ Bt, int ldb, int colBase,
    int kEnd, float (&acc)[4][8][4])
{
    const int tid  = threadIdx.x;
    const int lane = tid & 31;
    const int warp = tid >> 5;
    const int m0w  = (warp >> 1) * 64;
    const int n0w  = (warp & 1) * 64;
    const int ktiles = kEnd / BK;

    const __half* aSrc = A  + (size_t)(rowBase + tid) * lda;
    const __half* bSrc = Bt + (size_t)(colBase + tid) * ldb;
    const uint32_t sBase = (uint32_t)__cvta_generic_to_shared(sm_dyn);
    const uint32_t aDst0 = sBase + (uint32_t)(tid * A_ST) * 2u;
    const uint32_t bDst0 = sBase + (uint32_t)(STAGES * A_SZ + tid * A_ST) * 2u;

    #define LOAD_TILE(kt, slot)                                     \
    do {                                                            \
        uint32_t ad_ = aDst0 + (uint32_t)((slot) * A_SZ) * 2u;      \
        const __half* as_ = aSrc + (size_t)(kt) * BK;               \
        cp16(ad_,       as_);                                       \
        cp16(ad_ + 16u, as_ + 8);                                   \
        cp16(ad_ + 32u, as_ + 16);                                  \
        cp16(ad_ + 48u, as_ + 24);                                  \
        uint32_t bd_ = bDst0 + (uint32_t)((slot) * A_SZ) * 2u;      \
        const __half* bs_ = bSrc + (size_t)(kt) * BK;               \
        cp16(bd_,       bs_);                                       \
        cp16(bd_ + 16u, bs_ + 8);                                   \
        cp16(bd_ + 32u, bs_ + 16);                                  \
        cp16(bd_ + 48u, bs_ + 24);                                  \
    } while (0)

    LOAD_TILE(0, 0);
    asm volatile("cp.async.commit_group;");
    LOAD_TILE(1, 1);
    asm volatile("cp.async.commit_group;");

    const int rowOff = (lane & 7) + 8 * ((lane >> 3) & 1);
    const int colOff = (lane >> 4) * 8;     // halves

    int slot = 0;
    for (int kt = 0; kt < ktiles; kt++) {
        asm volatile("cp.async.wait_group 1;");
        __syncthreads();

        int nkt = kt + STAGES - 1;
        if (nkt < ktiles) {
            int ns = slot + STAGES - 1;
            if (ns >= STAGES) ns -= STAGES;
            LOAD_TILE(nkt, ns);
        }
        asm volatile("cp.async.commit_group;");

        const uint32_t asl = sBase + (uint32_t)(slot * A_SZ) * 2u;
        const uint32_t bsl = sBase + (uint32_t)((STAGES + slot) * A_SZ) * 2u;

        #pragma unroll
        for (int ks = 0; ks < BK; ks += 16) {
            uint32_t af[4][4], bf[8][2];
            #pragma unroll
            for (int mt = 0; mt < 4; mt++)
                ldsm4(af[mt], asl +
                      (uint32_t)((m0w + mt * 16 + rowOff) * A_ST + ks + colOff) * 2u);
            #pragma unroll
            for (int np = 0; np < 4; np++) {
                uint32_t t[4];
                ldsm4(t, bsl +
                      (uint32_t)((n0w + np * 16 + rowOff) * A_ST + ks + colOff) * 2u);
                bf[2 * np][0]     = t[0]; bf[2 * np][1]     = t[2];
                bf[2 * np + 1][0] = t[1]; bf[2 * np + 1][1] = t[3];
            }
            #pragma unroll
            for (int mt = 0; mt < 4; mt++)
                #pragma unroll
                for (int nt = 0; nt < 8; nt++)
                    mma16(acc[mt][nt], af[mt], bf[nt]);
        }

        if (++slot == STAGES) slot = 0;
    }
    #undef LOAD_TILE
}

// ---------------------------------------------------------------------------
// 64-row variant for qk: 64x128 CTA tile, 4 warps of 32x64.
// acc[mt 0..1][nt 0..7][4]
// ---------------------------------------------------------------------------
__device__ __forceinline__ void run_mma64(
    const __half* __restrict__ A, int lda, int rowBase,
    const __half* __restrict__ Bt, int ldb, int colBase,
    int kEnd, float (&acc)[2][8][4])
{
    const int tid  = threadIdx.x;
    const int lane = tid & 31;
    const int warp = tid >> 5;
    const int m0w  = (warp >> 1) * 32;
    const int n0w  = (warp & 1) * 64;
    const int ktiles = kEnd / BK;

    // A loader: 64 rows; thread t loads row t&63, 2x16B at seg (t>>6)*2
    const int aRow = tid & 63;
    const int aSeg = (tid >> 6) * 16;     // halves offset: 0 or 16
    const __half* aSrc = A  + (size_t)(rowBase + aRow) * lda + aSeg;
    const __half* bSrc = Bt + (size_t)(colBase + tid) * ldb;
    const uint32_t sBase = (uint32_t)__cvta_generic_to_shared(sm_dyn);
    const uint32_t aDst0 = sBase + (uint32_t)(aRow * A_ST + aSeg) * 2u;
    const uint32_t bDst0 = sBase + (uint32_t)(STAGES * A_SZ64 + tid * A_ST) * 2u;

    #define LOAD_TILE64(kt, slot)                                   \
    do {                                                            \
        uint32_t ad_ = aDst0 + (uint32_t)((slot) * A_SZ64) * 2u;    \
        const __half* as_ = aSrc + (size_t)(kt) * BK;               \
        cp16(ad_,       as_);                                       \
        cp16(ad_ + 16u, as_ + 8);                                   \
        uint32_t bd_ = bDst0 + (uint32_t)((slot) * A_SZ) * 2u;      \
        const __half* bs_ = bSrc + (size_t)(kt) * BK;               \
        cp16(bd_,       bs_);                                       \
        cp16(bd_ + 16u, bs_ + 8);                                   \
        cp16(bd_ + 32u, bs_ + 16);                                  \
        cp16(bd_ + 48u, bs_ + 24);                                  \
    } while (0)

    LOAD_TILE64(0, 0);
    asm volatile("cp.async.commit_group;");
    LOAD_TILE64(1, 1);
    asm volatile("cp.async.commit_group;");

    const int rowOff = (lane & 7) + 8 * ((lane >> 3) & 1);
    const int colOff = (lane >> 4) * 8;

    int slot = 0;
    for (int kt = 0; kt < ktiles; kt++) {
        asm volatile("cp.async.wait_group 1;");
        __syncthreads();

        int nkt = kt + STAGES - 1;
        if (nkt < ktiles) {
            int ns = slot + STAGES - 1;
            if (ns >= STAGES) ns -= STAGES;
            LOAD_TILE64(nkt, ns);
        }
        asm volatile("cp.async.commit_group;");

        const uint32_t asl = sBase + (uint32_t)(slot * A_SZ64) * 2u;
        const uint32_t bsl = sBase + (uint32_t)(STAGES * A_SZ64 * 0 +
                              (STAGES * A_SZ64 + slot * A_SZ)) * 2u;

        #pragma unroll
        for (int ks = 0; ks < BK; ks += 16) {
            uint32_t af[2][4], bf[8][2];
            #pragma unroll
            for (int mt = 0; mt < 2; mt++)
                ldsm4(af[mt], asl +
                      (uint32_t)((m0w + mt * 16 + rowOff) * A_ST + ks + colOff) * 2u);
            #pragma unroll
            for (int np = 0; np < 4; np++) {
                uint32_t t[4];
                ldsm4(t, bsl +
                      (uint32_t)((n0w + np * 16 + rowOff) * A_ST + ks + colOff) * 2u);
                bf[2 * np][0]     = t[0]; bf[2 * np][1]     = t[2];
                bf[2 * np + 1][0] = t[1]; bf[2 * np + 1][1] = t[3];
            }
            #pragma unroll
            for (int mt = 0; mt < 2; mt++)
                #pragma unroll
                for (int nt = 0; nt < 8; nt++)
                    mma16(acc[mt][nt], af[mt], bf[nt]);
        }

        if (++slot == STAGES) slot = 0;
    }
    #undef LOAD_TILE64
}

#define ACC_INIT(acc)                                   \
    _Pragma("unroll")                                   \
    for (int mt = 0; mt < 4; mt++)                      \
        _Pragma("unroll")                               \
        for (int nt = 0; nt < 8; nt++)                  \
            _Pragma("unroll")                           \
            for (int e = 0; e < 4; e++) acc[mt][nt][e] = 0.0f;

// Element (mt, nt, h, j):
//   row = rowBase + (warp>>1)*64 + mt*16 + (lane>>2) + h*8
//   col = colBase + (warp&1)*64 + nt*8 + (lane&3)*2 + j
#define EPI_PREAMBLE                                       \
    const int tid  = threadIdx.x;                          \
    const int lane = tid & 31;                             \
    const int warp = tid >> 5;                             \
    const int mBase = (warp >> 1) * 64 + (lane >> 2);      \
    const int nBase = (warp & 1) * 64 + (lane & 3) * 2;

// ---------------------------------------------------------------------------
// V (z=0): silu -> half, stored transposed per batch [Im][Sq] via smem.
// G (z=1): silu -> f32, [m][Im].  Merged into one launch (gridDim.z = 2).
// ---------------------------------------------------------------------------
__global__ void __launch_bounds__(NT, 2)
gemm_silu_kernel(const float* __restrict__ vb, const float* __restrict__ gb)
{
    const int which = blockIdx.z;
    const float* __restrict__ bias = which ? gb : vb;
    float acc[4][8][4];
    ACC_INIT(acc);
    run_mma(g_Xh, Dm, blockIdx.y * BM, which ? g_gWh : g_vWh, Dm,
            blockIdx.x * BN, Dm, acc);

    EPI_PREAMBLE;
    const int col0 = blockIdx.x * BN + nBase;
    if (which) {
        const int row0 = blockIdx.y * BM + mBase;
        #pragma unroll
        for (int mt = 0; mt < 4; mt++)
            #pragma unroll
            for (int nt = 0; nt < 8; nt++) {
                int c = col0 + nt * 8;
                float b0 = bias[c], b1 = bias[c + 1];
                #pragma unroll
                for (int h = 0; h < 2; h++) {
                    int r = row0 + mt * 16 + h * 8;
                    float2 o;
                    o.x = silu_f(acc[mt][nt][2 * h + 0] + b0);
                    o.y = silu_f(acc[mt][nt][2 * h + 1] + b1);
                    *(float2*)&g_G[(size_t)r * Im + c] = o;
                }
            }
    } else {
        const int b  = (blockIdx.y * BM) / Sq;
        const int sTile = blockIdx.y * BM - b * Sq;
        __half* __restrict__ Vt = g_Vh + (size_t)b * Im * Sq;
        __half* ts = (__half*)sm_dyn;                       // [128][VT_ST]

        asm volatile("cp.async.wait_all;");
        __syncthreads();                                    // ring buffer dead

        const int myHalf = warp >> 1;
        const int sLoc   = lane >> 2;
        #pragma unroll
        for (int h2 = 0; h2 < 2; h2++) {
            if (myHalf == h2) {
                #pragma unroll
                for (int mt = 0; mt < 4; mt++)
                    #pragma unroll
                    for (int nt = 0; nt < 8; nt++) {
                        int c = nBase + nt * 8;
                        float b0 = bias[col0 + nt * 8], b1 = bias[col0 + nt * 8 + 1];
                        #pragma unroll
                        for (int hh = 0; hh < 2; hh++) {
                            int s = sLoc + mt * 16 + hh * 8;     // 0..63
                            float v0 = silu_f(acc[mt][nt][2 * hh + 0] + b0);
                            float v1 = silu_f(acc[mt][nt][2 * hh + 1] + b1);
                            ts[c * VT_ST + s]       = __float2half_rn(v0);
                            ts[(c + 1) * VT_ST + s] = __float2half_rn(v1);
                        }
                    }
            }
            __syncthreads();
            #pragma unroll
            for (int p = 0; p < 16; p++) {
                int idx = tid + p * NT;          // 0..2047
                int c  = idx >> 4;               // 0..127
                int s4 = (idx & 15) << 2;        // 0..60
                uint2 v = *(const uint2*)&ts[c * VT_ST + s4];
                *(uint2*)&Vt[(size_t)(blockIdx.x * BN + c) * Sq
                             + sTile + h2 * 64 + s4] = v;
            }
            __syncthreads();
        }
    }
}

// ---------------------------------------------------------------------------
// base = silu(X @ inW + inb);  Q/K = affine(base), half.  BM=64 (grid 128).
// ---------------------------------------------------------------------------
__global__ void __launch_bounds__(NT, 2)
gemm_qk_kernel(const float* __restrict__ inb,
               const float* __restrict__ qg, const float* __restrict__ qb,
               const float* __restrict__ kg, const float* __restrict__ kb)
{
    float acc[2][8][4];
    #pragma unroll
    for (int mt = 0; mt < 2; mt++)
        #pragma unroll
        for (int nt = 0; nt < 8; nt++)
            #pragma unroll
            for (int e = 0; e < 4; e++) acc[mt][nt][e] = 0.0f;

    run_mma64(g_Xh, Dm, blockIdx.y * 64, g_inWh, Dm, 0, Dm, acc);

    const int tid  = threadIdx.x;
    const int lane = tid & 31;
    const int warp = tid >> 5;
    const int mBase = (warp >> 1) * 32 + (lane >> 2);
    const int nBase = (warp & 1) * 64 + (lane & 3) * 2;
    const int row0 = blockIdx.y * 64 + mBase;
    #pragma unroll
    for (int mt = 0; mt < 2; mt++)
        #pragma unroll
        for (int nt = 0; nt < 8; nt++) {
            int c = nBase + nt * 8;
            float g0q = qg[c], g1q = qg[c + 1], b0q = qb[c], b1q = qb[c + 1];
            float g0k = kg[c], g1k = kg[c + 1], b0k = kb[c], b1k = kb[c + 1];
            float i0 = inb[c], i1 = inb[c + 1];
            #pragma unroll
            for (int h = 0; h < 2; h++) {
                int r = row0 + mt * 16 + h * 8;
                float s0 = silu_f(acc[mt][nt][2 * h + 0] + i0);
                float s1 = silu_f(acc[mt][nt][2 * h + 1] + i1);
                size_t idx = (size_t)r * Dh + c;
                *(__half2*)&g_Qh[idx] =
                    __floats2half2_rn(s0 * g0q + b0q, s1 * g1q + b1q);
                *(__half2*)&g_Kh[idx] =
                    __floats2half2_rn(s0 * g0k + b0k, s1 * g1k + b1k);
            }
        }
}

// ---------------------------------------------------------------------------
// A[b] = relu(Q K^T / sqrt(1536) + bias)^2, causal; half out.
// ---------------------------------------------------------------------------
__global__ void __launch_bounds__(NT, 2)
scores_kernel()
{
    if (blockIdx.x > blockIdx.y) return;

    const int z  = blockIdx.z;
    const int i0 = blockIdx.y * BM;
    const int j0 = blockIdx.x * BN;
    __half* __restrict__ Ab = g_Ah + (size_t)z * Sq * Sq;

    float acc[4][8][4];
    ACC_INIT(acc);
    run_mma(g_Qh + (size_t)z * Sq * Dh, Dh, i0,
            g_Kh + (size_t)z * Sq * Dh, Dh, j0, Dh, acc);

    EPI_PREAMBLE;
    const float rscale = 1.0f / sqrtf((float)Im);
    const int gi0 = i0 + mBase;
    const int gj0 = j0 + nBase;
    #pragma unroll
    for (int mt = 0; mt < 4; mt++)
        #pragma unroll
        for (int nt = 0; nt < 8; nt++) {
            #pragma unroll
            for (int h = 0; h < 2; h++) {
                int gi = gi0 + mt * 16 + h * 8;
                int gj = gj0 + nt * 8;
                float v0 = 0.0f, v1 = 0.0f;
                if (gj <= gi) {
                    float s = acc[mt][nt][2 * h] * rscale + g_bias[gi - gj];
                    v0 = (s > 0.0f) ? s * s : 0.0f;
                }
                if (gj + 1 <= gi) {
                    float s = acc[mt][nt][2 * h + 1] * rscale + g_bias[gi - gj - 1];
                    v1 = (s > 0.0f) ? s * s : 0.0f;
                }
                *(__half2*)&Ab[(size_t)gi * Sq + gj] = __floats2half2_rn(v0, v1);
            }
        }
}

// ---------------------------------------------------------------------------
// O[b] = (A[b] @ V[b]) * G[b]; half out.  Causal k-limit.
// ---------------------------------------------------------------------------
__global__ void __launch_bounds__(NT, 2)
gemm_av_gate_kernel()
{
    const int z = blockIdx.z;
    float acc[4][8][4];
    ACC_INIT(acc);
    const int kEnd = blockIdx.y * BM + BM;
    run_mma(g_Ah + (size_t)z * Sq * Sq, Sq, blockIdx.y * BM,
            g_Vh + (size_t)z * Im * Sq, Sq, blockIdx.x * BN, kEnd, acc);

    EPI_PREAMBLE;
    const int row0 = z * Sq + blockIdx.y * BM + mBase;
    const int col0 = blockIdx.x * BN + nBase;
    #pragma unroll
    for (int mt = 0; mt < 4; mt++)
        #pragma unroll
        for (int nt = 0; nt < 8; nt++) {
            int c = col0 + nt * 8;
            #pragma unroll
            for (int h = 0; h < 2; h++) {
                int r = row0 + mt * 16 + h * 8;
                size_t idx = (size_t)r * Im + c;
                float2 g = *(const float2*)&g_G[idx];
                *(__half2*)&g_Oh[idx] =
                    __floats2half2_rn(acc[mt][nt][2 * h + 0] * g.x,
                                      acc[mt][nt][2 * h + 1] * g.y);
            }
        }
}

// ---------------------------------------------------------------------------
// out = O @ out_W + out_b   (f32 output)
// ---------------------------------------------------------------------------
__global__ void __launch_bounds__(NT, 2)
gemm_out_kernel(const float* __restrict__ bias, float* __restrict__ out)
{
    float acc[4][8][4];
    ACC_INIT(acc);
    run_mma(g_Oh, Im, blockIdx.y * BM, g_oWh, Im, blockIdx.x * BN, Im, acc);

    EPI_PREAMBLE;
    const int row0 = blockIdx.y * BM + mBase;
    const int col0 = blockIdx.x * BN + nBase;
    #pragma unroll
    for (int mt = 0; mt < 4; mt++)
        #pragma unroll
        for (int nt = 0; nt < 8; nt++) {
            int c = col0 + nt * 8;
            float b0 = bias[c], b1 = bias[c + 1];
            #pragma unroll
            for (int h = 0; h < 2; h++) {
                int r = row0 + mt * 16 + h * 8;
                float2 o;
                o.x = acc[mt][nt][2 * h + 0] + b0;
                o.y = acc[mt][nt][2 * h + 1] + b1;
                *(float2*)&out[(size_t)r * Dm + c] = o;
            }
        }
}

// ---------------------------------------------------------------------------
// Launch (input order auto-detected from in_sizes[0])
// ---------------------------------------------------------------------------
extern "C" void kernel_launch(void* const* d_in, const int* in_sizes, int n_in,
                              void* d_out, int out_size)
{
    const float *x, *vW, *vb, *gW, *gb, *inW, *inb;
    const float *qg, *qb, *kg, *kb, *oW, *ob, *rel;

    if (in_sizes[0] == Bsz * Sq * Dm) {
        x   = (const float*)d_in[0];
        vW  = (const float*)d_in[1];
        vb  = (const float*)d_in[2];
        gW  = (const float*)d_in[3];
        gb  = (const float*)d_in[4];
        inW = (const float*)d_in[5];
        inb = (const float*)d_in[6];
        qg  = (const float*)d_in[7];
        qb  = (const float*)d_in[8];
        kg  = (const float*)d_in[9];
        kb  = (const float*)d_in[10];
        oW  = (const float*)d_in[11];
        ob  = (const float*)d_in[12];
        rel = (const float*)d_in[13];
    } else {
        gW  = (const float*)d_in[0];
        gb  = (const float*)d_in[1];
        inW = (const float*)d_in[2];
        inb = (const float*)d_in[3];
        kb  = (const float*)d_in[4];
        kg  = (const float*)d_in[5];
        oW  = (const float*)d_in[6];
        ob  = (const float*)d_in[7];
        qb  = (const float*)d_in[8];
        qg  = (const float*)d_in[9];
        rel = (const float*)d_in[10];
        vW  = (const float*)d_in[11];
        vb  = (const float*)d_in[12];
        x   = (const float*)d_in[13];
    }

    float* out = (float*)d_out;

    static bool attr_done = false;
    if (!attr_done) {
        cudaFuncSetAttribute(gemm_silu_kernel,
            cudaFuncAttributeMaxDynamicSharedMemorySize, SMEM_BYTES);
        cudaFuncSetAttribute(gemm_qk_kernel,
            cudaFuncAttributeMaxDynamicSharedMemorySize, SMEM_BYTES64);
        cudaFuncSetAttribute(scores_kernel,
            cudaFuncAttributeMaxDynamicSharedMemorySize, SMEM_BYTES);
        cudaFuncSetAttribute(gemm_av_gate_kernel,
            cudaFuncAttributeMaxDynamicSharedMemorySize, SMEM_BYTES);
        cudaFuncSetAttribute(gemm_out_kernel,
            cudaFuncAttributeMaxDynamicSharedMemorySize, SMEM_BYTES);
        attr_done = true;
    }

    // single fused prologue launch
    fused_prologue_kernel<<<PRO_TOT, 256>>>(x, vW, gW, inW, oW, rel);

    dim3 blk(NT);
    gemm_silu_kernel<<<dim3(Im / BN, Mtot / BM, 2), blk, SMEM_BYTES>>>(vb, gb);
    gemm_qk_kernel  <<<dim3(1, Mtot / 64), blk, SMEM_BYTES64>>>(inb, qg, qb, kg, kb);
    scores_kernel   <<<dim3(Sq / BN, Sq / BM, Bsz), blk, SMEM_BYTES>>>();
    gemm_av_gate_kernel<<<dim3(Im / BN, Sq / BM, Bsz), blk, SMEM_BYTES>>>();
    gemm_out_kernel <<<dim3(Dm / BN, Mtot / BM), blk, SMEM_BYTES>>>(ob, out);
}